// round 2
// baseline (speedup 1.0000x reference)
#include <cuda_runtime.h>

#define N_NODES 16384
#define NCH 64

// Scratch (allocation-free: device globals)
__device__ __align__(16) float g_seqT[N_NODES * NCH];   // node-major seq
__device__ __align__(16) float g_accT[N_NODES * NCH];   // node-major scatter-add accumulator
__device__ unsigned int g_deg[N_NODES];

// ---------------------------------------------------------------------------
// Kernel 1: transpose seq (c-major [64,16384]) -> seqT (node-major [16384,64]),
// and zero accT / deg. Grid (512, 2), block (32, 32).
// ---------------------------------------------------------------------------
__global__ void prep_kernel(const float* __restrict__ seq) {
    __shared__ float tile[32][33];
    int nBase = blockIdx.x * 32;
    int cBase = blockIdx.y * 32;
    int tx = threadIdx.x, ty = threadIdx.y;

    // coalesced read: consecutive tx -> consecutive node index
    tile[ty][tx] = seq[(cBase + ty) * N_NODES + (nBase + tx)];
    __syncthreads();
    // coalesced write: consecutive tx -> consecutive channel
    g_seqT[(nBase + ty) * NCH + (cBase + tx)] = tile[tx][ty];

    // zero accT (1M floats over 1024 blocks x 1024 threads) and deg
    int lin = (blockIdx.y * gridDim.x + blockIdx.x) * 1024 + ty * 32 + tx;
    g_accT[lin] = 0.0f;
    if (lin < N_NODES) g_deg[lin] = 0u;
}

// ---------------------------------------------------------------------------
// Kernel 2: edge scatter-add. idx is INT32 (JAX x64 disabled -> int64 aliases
// int32). 16 lanes per edge; lane 'part' handles channels [4*part, 4*part+4).
// Edge pair loaded once per 16-lane group (int2), shfl-broadcast.
// accT[a] += seqT[b] (red.global.add.v4.f32), deg[a] += 1.
// ---------------------------------------------------------------------------
__global__ void edge_kernel(const int* __restrict__ idx, int M) {
    int t = blockIdx.x * blockDim.x + threadIdx.x;
    int m = t >> 4;
    int part = t & 15;
    int lane = threadIdx.x & 31;

    int a0 = 0, b0 = 0;
    if (m < M && part == 0) {
        int2 p = ((const int2*)idx)[m];
        a0 = p.x;   // segment / k=0 node
        b0 = p.y;   // k=1 gather node
    }
    unsigned mask = 0xffffffffu;
    int a = __shfl_sync(mask, a0, lane & 16);
    int b = __shfl_sync(mask, b0, lane & 16);
    if (m >= M) return;

    float4 v = ((const float4*)g_seqT)[b * 16 + part];
    float4* dst = ((float4*)g_accT) + (a * 16 + part);
    asm volatile("red.global.add.v4.f32 [%0], {%1, %2, %3, %4};"
                 :: "l"(dst), "f"(v.x), "f"(v.y), "f"(v.z), "f"(v.w)
                 : "memory");
    if (part == 0) atomicAdd(&g_deg[a], 1u);
}

// ---------------------------------------------------------------------------
// Kernel 3: combine. out[o,n] = deg[n]*sum_c W0[o,c]*seq[c,n] + sum_c W1[o,c]*g[c,n]
// Block: 512 threads, 8 nodes per block. W staged in smem as [c][o].
// Thread (o = tid>>3, j = tid&7) computes out[o, nodeBase+j].
// ---------------------------------------------------------------------------
__global__ void out_kernel(const float* __restrict__ W, float* __restrict__ out) {
    __shared__ float Ws0[64 * 64];   // [c][o]
    __shared__ float Ws1[64 * 64];   // [c][o]
    __shared__ float hs[8][65];      // deg[n] * seqT[n][c]  (padded)
    __shared__ float gs[8][65];      // accT[n][c]           (padded)

    int tid = threadIdx.x;

    // stage W: W[o][c][k] with shape (64,64,2) row-major
    #pragma unroll
    for (int i = tid; i < 4096; i += 512) {
        int o = i >> 6, c = i & 63;
        Ws0[c * 64 + o] = W[(o * 64 + c) * 2 + 0];
        Ws1[c * 64 + o] = W[(o * 64 + c) * 2 + 1];
    }

    int nodeBase = blockIdx.x * 8;
    {
        int j = tid >> 6, c = tid & 63;   // 512 threads = 8 nodes x 64 ch
        int n = nodeBase + j;
        float d = (float)g_deg[n];
        hs[j][c] = d * g_seqT[n * NCH + c];
        gs[j][c] = g_accT[n * NCH + c];
    }
    __syncthreads();

    int j = tid & 7;
    int o = tid >> 3;
    float acc = 0.0f;
    #pragma unroll
    for (int c = 0; c < 64; c++) {
        acc = fmaf(Ws0[c * 64 + o], hs[j][c],
              fmaf(Ws1[c * 64 + o], gs[j][c], acc));
    }
    out[o * N_NODES + (nodeBase + j)] = acc;
}

// ---------------------------------------------------------------------------
extern "C" void kernel_launch(void* const* d_in, const int* in_sizes, int n_in,
                              void* d_out, int out_size) {
    const float* seq = (const float*)d_in[0];   // (1,64,16384) f32
    const int*   idx = (const int*)d_in[1];     // (2M,) int32 (jax x64 off)
    const float* W   = (const float*)d_in[2];   // (64,64,2) f32
    float*       out = (float*)d_out;           // (1,64,16384) f32

    int twoM = in_sizes[1];
    int M = twoM / 2;

    dim3 pb(32, 32);
    dim3 pg(N_NODES / 32, NCH / 32);
    prep_kernel<<<pg, pb>>>(seq);

    long long totalThreads = (long long)M * 16;
    int blocks = (int)((totalThreads + 255) / 256);
    edge_kernel<<<blocks, 256>>>(idx, M);

    out_kernel<<<N_NODES / 8, 512>>>(W, out);
}

// round 3
// speedup vs baseline: 1.2631x; 1.2631x over previous
#include <cuda_runtime.h>

#define N_NODES 16384
#define NCH 64
#define MAX_EDGES (1 << 19)   // M = 524288

// Scratch (allocation-free: device globals)
__device__ __align__(16) float g_seqT[N_NODES * NCH];   // node-major seq
__device__ __align__(16) float g_accT[N_NODES * NCH];   // node-major gathered sums
__device__ unsigned int g_deg[N_NODES];
__device__ int g_rowptr[N_NODES + 1];
__device__ int g_cursor[N_NODES];
__device__ int g_csrb[MAX_EDGES];

// ---------------------------------------------------------------------------
// K1: transpose seq [64,16384] -> seqT [16384,64]; zero deg.
// Grid (512,2), block (32,8), 4 elems/thread.
// ---------------------------------------------------------------------------
__global__ void prep_kernel(const float* __restrict__ seq) {
    __shared__ float tile[32][33];
    int nBase = blockIdx.x * 32;
    int cBase = blockIdx.y * 32;
    int tx = threadIdx.x, ty = threadIdx.y;

    #pragma unroll
    for (int r = 0; r < 4; r++)
        tile[ty + 8 * r][tx] = seq[(cBase + ty + 8 * r) * N_NODES + nBase + tx];
    __syncthreads();
    #pragma unroll
    for (int r = 0; r < 4; r++)
        g_seqT[(nBase + ty + 8 * r) * NCH + cBase + tx] = tile[tx][ty + 8 * r];

    int lin = (blockIdx.y * gridDim.x + blockIdx.x) * 256 + ty * 32 + tx;
    if (lin < N_NODES) g_deg[lin] = 0u;
}

// ---------------------------------------------------------------------------
// K2: histogram of segment indices (idx[2m]).
// ---------------------------------------------------------------------------
__global__ void hist_kernel(const int* __restrict__ idx, int M) {
    int m = blockIdx.x * blockDim.x + threadIdx.x;
    if (m < M) {
        int a = ((const int2*)idx)[m].x;
        atomicAdd(&g_deg[a], 1u);
    }
}

// ---------------------------------------------------------------------------
// K3: exclusive scan of deg -> rowptr (and cursor copy). Single block, 1024
// threads, 16 elems/thread.
// ---------------------------------------------------------------------------
__global__ void scan_kernel() {
    __shared__ int warpsums[32];
    int t = threadIdx.x;
    int base = t * 16;

    int d[16];
    const int4* dp = (const int4*)((const int*)g_deg + base);
    #pragma unroll
    for (int q = 0; q < 4; q++) {
        int4 v = dp[q];
        d[q * 4 + 0] = v.x; d[q * 4 + 1] = v.y;
        d[q * 4 + 2] = v.z; d[q * 4 + 3] = v.w;
    }
    int tot = 0;
    #pragma unroll
    for (int i = 0; i < 16; i++) tot += d[i];

    // warp inclusive scan of thread totals
    int lane = t & 31, wid = t >> 5;
    int x = tot;
    #pragma unroll
    for (int off = 1; off < 32; off <<= 1) {
        int y = __shfl_up_sync(0xffffffffu, x, off);
        if (lane >= off) x += y;
    }
    if (lane == 31) warpsums[wid] = x;
    __syncthreads();
    if (wid == 0) {
        int w = warpsums[lane];
        #pragma unroll
        for (int off = 1; off < 32; off <<= 1) {
            int y = __shfl_up_sync(0xffffffffu, w, off);
            if (lane >= off) w += y;
        }
        warpsums[lane] = w;
    }
    __syncthreads();
    int blockoff = (wid > 0) ? warpsums[wid - 1] : 0;
    int ex = blockoff + x - tot;   // exclusive prefix of this thread's chunk

    #pragma unroll
    for (int i = 0; i < 16; i++) {
        g_rowptr[base + i] = ex;
        g_cursor[base + i] = ex;
        ex += d[i];
    }
    if (t == 1023) g_rowptr[N_NODES] = ex;
}

// ---------------------------------------------------------------------------
// K4: scatter edge b-indices into CSR order.
// ---------------------------------------------------------------------------
__global__ void scatter_kernel(const int* __restrict__ idx, int M) {
    int m = blockIdx.x * blockDim.x + threadIdx.x;
    if (m < M) {
        int2 p = ((const int2*)idx)[m];
        int pos = atomicAdd(&g_cursor[p.x], 1);
        g_csrb[pos] = p.y;
    }
}

// ---------------------------------------------------------------------------
// K5: gather-sum. One warp per node: accT[n] = sum over edges of seqT[b].
// Lane l holds channels [2l, 2l+2). 32 edges batched per shfl round.
// ---------------------------------------------------------------------------
__global__ void gather_kernel() {
    int n = (blockIdx.x << 3) + (threadIdx.x >> 5);   // 8 warps/block
    int lane = threadIdx.x & 31;
    int start = g_rowptr[n];
    int end = g_rowptr[n + 1];

    const float2* sp = (const float2*)g_seqT;
    float2 acc = make_float2(0.0f, 0.0f);

    for (int e0 = start; e0 < end; e0 += 32) {
        int nb = end - e0;
        if (nb > 32) nb = 32;
        int b = 0;
        if (lane < nb) b = g_csrb[e0 + lane];
        if (nb == 32) {
            #pragma unroll
            for (int i = 0; i < 32; i++) {
                int bi = __shfl_sync(0xffffffffu, b, i);
                float2 v = sp[bi * 32 + lane];
                acc.x += v.x; acc.y += v.y;
            }
        } else {
            for (int i = 0; i < nb; i++) {
                int bi = __shfl_sync(0xffffffffu, b, i);
                float2 v = sp[bi * 32 + lane];
                acc.x += v.x; acc.y += v.y;
            }
        }
    }
    ((float2*)g_accT)[n * 32 + lane] = acc;
}

// ---------------------------------------------------------------------------
// K6: combine. out[o,n] = deg[n]*sum_c W0[o,c]*seqT[n,c] + sum_c W1[o,c]*accT[n,c]
// Block: 128 threads, 8 nodes. Thread (j = tid&7, og = tid>>3) computes
// outputs o = og*4 .. og*4+3 for node nodeBase+j. float4 register blocking.
// ---------------------------------------------------------------------------
__global__ void out_kernel(const float* __restrict__ W, float* __restrict__ out) {
    __shared__ float4 Ws0[64 * 16];   // [c][og]
    __shared__ float4 Ws1[64 * 16];   // [c][og]
    __shared__ float hs[8][65];       // deg * seqT
    __shared__ float gs[8][65];       // accT

    int tid = threadIdx.x;

    // stage W: W[o][c][k], shape (64,64,2) row-major
    for (int i = tid; i < 1024; i += 128) {
        int c = i >> 4, og = i & 15;
        int o = og * 4;
        float4 w0, w1;
        w0.x = W[((o + 0) * 64 + c) * 2 + 0]; w1.x = W[((o + 0) * 64 + c) * 2 + 1];
        w0.y = W[((o + 1) * 64 + c) * 2 + 0]; w1.y = W[((o + 1) * 64 + c) * 2 + 1];
        w0.z = W[((o + 2) * 64 + c) * 2 + 0]; w1.z = W[((o + 2) * 64 + c) * 2 + 1];
        w0.w = W[((o + 3) * 64 + c) * 2 + 0]; w1.w = W[((o + 3) * 64 + c) * 2 + 1];
        Ws0[i] = w0; Ws1[i] = w1;
    }

    int nodeBase = blockIdx.x * 8;
    for (int i = tid; i < 512; i += 128) {
        int j = i >> 6, c = i & 63;
        int n = nodeBase + j;
        float d = (float)g_deg[n];
        hs[j][c] = d * g_seqT[n * NCH + c];
        gs[j][c] = g_accT[n * NCH + c];
    }
    __syncthreads();

    int j = tid & 7;       // node within block (warp-contiguous for store coalescing)
    int og = tid >> 3;     // output group
    float4 acc = make_float4(0.f, 0.f, 0.f, 0.f);
    #pragma unroll
    for (int c = 0; c < 64; c++) {
        float h = hs[j][c], g = gs[j][c];
        float4 w0 = Ws0[c * 16 + og], w1 = Ws1[c * 16 + og];
        acc.x += w0.x * h + w1.x * g;
        acc.y += w0.y * h + w1.y * g;
        acc.z += w0.z * h + w1.z * g;
        acc.w += w0.w * h + w1.w * g;
    }
    int o = og * 4, n = nodeBase + j;
    out[(o + 0) * N_NODES + n] = acc.x;
    out[(o + 1) * N_NODES + n] = acc.y;
    out[(o + 2) * N_NODES + n] = acc.z;
    out[(o + 3) * N_NODES + n] = acc.w;
}

// ---------------------------------------------------------------------------
extern "C" void kernel_launch(void* const* d_in, const int* in_sizes, int n_in,
                              void* d_out, int out_size) {
    const float* seq = (const float*)d_in[0];   // (1,64,16384) f32
    const int*   idx = (const int*)d_in[1];     // (2M,) int32
    const float* W   = (const float*)d_in[2];   // (64,64,2) f32
    float*       out = (float*)d_out;           // (1,64,16384) f32

    int twoM = in_sizes[1];
    int M = twoM / 2;
    int eb = (M + 255) / 256;

    prep_kernel<<<dim3(N_NODES / 32, NCH / 32), dim3(32, 8)>>>(seq);
    hist_kernel<<<eb, 256>>>(idx, M);
    scan_kernel<<<1, 1024>>>();
    scatter_kernel<<<eb, 256>>>(idx, M);
    gather_kernel<<<N_NODES / 8, 256>>>();
    out_kernel<<<N_NODES / 8, 128>>>(W, out);
}

// round 4
// speedup vs baseline: 1.7575x; 1.3914x over previous
#include <cuda_runtime.h>

#define N_NODES 16384
#define NCH 64
#define MAX_EDGES (1 << 19)

// Scratch (allocation-free: device globals, zero-initialized at load)
__device__ __align__(16) float g_seqT[N_NODES * NCH];     // node-major seq
__device__ __align__(16) unsigned int g_deg[N_NODES];     // zeroed by scan after use
__device__ int g_rowptr[N_NODES + 1];
__device__ int g_cursor[N_NODES];
__device__ int g_csrb[MAX_EDGES];

// ---------------------------------------------------------------------------
// K1 (fused): blocks [0,1024) transpose seq -> seqT; blocks [1024,..) histogram
// segment indices into g_deg (4 edges/thread, int4 loads, independent atomics).
// g_deg is zero on entry: statically zero-init on first call, re-zeroed by the
// scan kernel on every subsequent call/replay.
// ---------------------------------------------------------------------------
__global__ void prep_hist_kernel(const float* __restrict__ seq,
                                 const int* __restrict__ idx, int M) {
    int b = blockIdx.x;
    int tid = threadIdx.x;
    if (b < 1024) {
        __shared__ float tile[32][33];
        int bx = b & 511, by = b >> 9;
        int nBase = bx * 32, cBase = by * 32;
        int tx = tid & 31, ty = tid >> 5;   // ty in [0,8)
        #pragma unroll
        for (int r = 0; r < 4; r++)
            tile[ty + 8 * r][tx] = seq[(cBase + ty + 8 * r) * N_NODES + nBase + tx];
        __syncthreads();
        #pragma unroll
        for (int r = 0; r < 4; r++)
            g_seqT[(nBase + ty + 8 * r) * NCH + cBase + tx] = tile[tx][ty + 8 * r];
    } else {
        int hb = b - 1024;
        int m0 = (hb * 256 + tid) * 4;
        if (m0 + 3 < M) {
            const int4* p = (const int4*)idx + (m0 >> 1);
            int4 v0 = p[0], v1 = p[1];
            atomicAdd(&g_deg[v0.x], 1u);
            atomicAdd(&g_deg[v0.z], 1u);
            atomicAdd(&g_deg[v1.x], 1u);
            atomicAdd(&g_deg[v1.z], 1u);
        } else {
            for (int m = m0; m < M; m++)
                atomicAdd(&g_deg[idx[2 * m]], 1u);
        }
    }
}

// ---------------------------------------------------------------------------
// K2: exclusive scan deg -> rowptr/cursor; re-zero deg (replay safety).
// Single block, 1024 threads, 16 elems/thread.
// ---------------------------------------------------------------------------
__global__ void scan_kernel() {
    __shared__ int warpsums[32];
    int t = threadIdx.x;
    int base = t * 16;

    int d[16];
    int4* dp = (int4*)((int*)g_deg + base);
    #pragma unroll
    for (int q = 0; q < 4; q++) {
        int4 v = dp[q];
        d[q * 4 + 0] = v.x; d[q * 4 + 1] = v.y;
        d[q * 4 + 2] = v.z; d[q * 4 + 3] = v.w;
    }
    // restore deg to zero for next invocation/replay
    int4 z = make_int4(0, 0, 0, 0);
    #pragma unroll
    for (int q = 0; q < 4; q++) dp[q] = z;

    int tot = 0;
    #pragma unroll
    for (int i = 0; i < 16; i++) tot += d[i];

    int lane = t & 31, wid = t >> 5;
    int x = tot;
    #pragma unroll
    for (int off = 1; off < 32; off <<= 1) {
        int y = __shfl_up_sync(0xffffffffu, x, off);
        if (lane >= off) x += y;
    }
    if (lane == 31) warpsums[wid] = x;
    __syncthreads();
    if (wid == 0) {
        int w = warpsums[lane];
        #pragma unroll
        for (int off = 1; off < 32; off <<= 1) {
            int y = __shfl_up_sync(0xffffffffu, w, off);
            if (lane >= off) w += y;
        }
        warpsums[lane] = w;
    }
    __syncthreads();
    int blockoff = (wid > 0) ? warpsums[wid - 1] : 0;
    int ex = blockoff + x - tot;

    #pragma unroll
    for (int i = 0; i < 16; i++) {
        g_rowptr[base + i] = ex;
        g_cursor[base + i] = ex;
        ex += d[i];
    }
    if (t == 1023) g_rowptr[N_NODES] = ex;
}

// ---------------------------------------------------------------------------
// K3: scatter edge b-indices into CSR order. 4 edges/thread for atomic MLP.
// ---------------------------------------------------------------------------
__global__ void scatter_kernel(const int* __restrict__ idx, int M) {
    int tid = threadIdx.x;
    int m0 = (blockIdx.x * 256 + tid) * 4;
    if (m0 + 3 < M) {
        const int4* p = (const int4*)idx + (m0 >> 1);
        int4 v0 = p[0], v1 = p[1];
        int p0 = atomicAdd(&g_cursor[v0.x], 1);
        int p1 = atomicAdd(&g_cursor[v0.z], 1);
        int p2 = atomicAdd(&g_cursor[v1.x], 1);
        int p3 = atomicAdd(&g_cursor[v1.z], 1);
        g_csrb[p0] = v0.y;
        g_csrb[p1] = v0.w;
        g_csrb[p2] = v1.y;
        g_csrb[p3] = v1.w;
    } else {
        for (int m = m0; m < M; m++) {
            int a = idx[2 * m], bb = idx[2 * m + 1];
            int pos = atomicAdd(&g_cursor[a], 1);
            g_csrb[pos] = bb;
        }
    }
}

// ---------------------------------------------------------------------------
// K4 (fused gather + combine): 256 blocks x 512 threads, 64 nodes per block.
// Phase A: warp w gathers nodes j = w + 16*i (i=0..3): acc = sum seqT[b],
//          h = deg * seqT[n]; staged into smem as [c][node] (pad 65).
// Phase B: out[o,n] = sum_c W0[o,c]*h[c,n] + W1[o,c]*g[c,n].
//          Thread (j=tid&63, og=tid>>6) computes 8 outputs for node j.
// Dynamic smem: Ws0/Ws1 (2*16KB) + hs/gs (2*16.6KB) = 66048 B.
// ---------------------------------------------------------------------------
__global__ void gather_out_kernel(const float* __restrict__ W,
                                  float* __restrict__ out) {
    extern __shared__ float smem[];
    float4* Ws0 = (float4*)smem;          // [c][16] float4  (o = q*4..q*4+3)
    float4* Ws1 = Ws0 + 64 * 16;
    float* hs = (float*)(Ws1 + 64 * 16);  // [64][65]  deg * seqT
    float* gs = hs + 64 * 65;             // [64][65]  gathered sums

    int tid = threadIdx.x;
    int lane = tid & 31;
    int w = tid >> 5;                     // 16 warps
    int nodeBase = blockIdx.x * 64;

    // stage W: W[o][c][k], shape (64,64,2) row-major
    for (int i = tid; i < 1024; i += 512) {
        int c = i >> 4, q = i & 15;
        int o = q * 4;
        float4 w0, w1;
        w0.x = W[((o + 0) * 64 + c) * 2 + 0]; w1.x = W[((o + 0) * 64 + c) * 2 + 1];
        w0.y = W[((o + 1) * 64 + c) * 2 + 0]; w1.y = W[((o + 1) * 64 + c) * 2 + 1];
        w0.z = W[((o + 2) * 64 + c) * 2 + 0]; w1.z = W[((o + 2) * 64 + c) * 2 + 1];
        w0.w = W[((o + 3) * 64 + c) * 2 + 0]; w1.w = W[((o + 3) * 64 + c) * 2 + 1];
        Ws0[c * 16 + q] = w0;
        Ws1[c * 16 + q] = w1;
    }

    // Phase A: gather. Lane holds channels 2*lane, 2*lane+1.
    const float2* sp = (const float2*)g_seqT;
    #pragma unroll
    for (int i = 0; i < 4; i++) {
        int j = w + 16 * i;               // local node
        int n = nodeBase + j;
        int start = g_rowptr[n];
        int end = g_rowptr[n + 1];
        float2 acc = make_float2(0.0f, 0.0f);

        for (int e0 = start; e0 < end; e0 += 32) {
            int nb = end - e0;
            if (nb > 32) nb = 32;
            int b = 0;
            if (lane < nb) b = g_csrb[e0 + lane];
            if (nb == 32) {
                #pragma unroll
                for (int k = 0; k < 32; k++) {
                    int bi = __shfl_sync(0xffffffffu, b, k);
                    float2 v = sp[bi * 32 + lane];
                    acc.x += v.x; acc.y += v.y;
                }
            } else {
                for (int k = 0; k < nb; k++) {
                    int bi = __shfl_sync(0xffffffffu, b, k);
                    float2 v = sp[bi * 32 + lane];
                    acc.x += v.x; acc.y += v.y;
                }
            }
        }
        float deg = (float)(end - start);
        float2 sv = sp[n * 32 + lane];
        hs[(2 * lane + 0) * 65 + j] = deg * sv.x;
        hs[(2 * lane + 1) * 65 + j] = deg * sv.y;
        gs[(2 * lane + 0) * 65 + j] = acc.x;
        gs[(2 * lane + 1) * 65 + j] = acc.y;
    }
    __syncthreads();

    // Phase B: combine
    int j = tid & 63;
    int og = tid >> 6;                    // 0..7, outputs o = og*8 .. og*8+7
    float4 a0 = make_float4(0.f, 0.f, 0.f, 0.f);
    float4 a1 = make_float4(0.f, 0.f, 0.f, 0.f);
    #pragma unroll
    for (int c = 0; c < 64; c++) {
        float h = hs[c * 65 + j];
        float g = gs[c * 65 + j];
        float4 w00 = Ws0[c * 16 + og * 2 + 0];
        float4 w01 = Ws0[c * 16 + og * 2 + 1];
        float4 w10 = Ws1[c * 16 + og * 2 + 0];
        float4 w11 = Ws1[c * 16 + og * 2 + 1];
        a0.x += w00.x * h + w10.x * g;
        a0.y += w00.y * h + w10.y * g;
        a0.z += w00.z * h + w10.z * g;
        a0.w += w00.w * h + w10.w * g;
        a1.x += w01.x * h + w11.x * g;
        a1.y += w01.y * h + w11.y * g;
        a1.z += w01.z * h + w11.z * g;
        a1.w += w01.w * h + w11.w * g;
    }
    int o = og * 8;
    int n = nodeBase + j;
    out[(o + 0) * N_NODES + n] = a0.x;
    out[(o + 1) * N_NODES + n] = a0.y;
    out[(o + 2) * N_NODES + n] = a0.z;
    out[(o + 3) * N_NODES + n] = a0.w;
    out[(o + 4) * N_NODES + n] = a1.x;
    out[(o + 5) * N_NODES + n] = a1.y;
    out[(o + 6) * N_NODES + n] = a1.z;
    out[(o + 7) * N_NODES + n] = a1.w;
}

// ---------------------------------------------------------------------------
extern "C" void kernel_launch(void* const* d_in, const int* in_sizes, int n_in,
                              void* d_out, int out_size) {
    const float* seq = (const float*)d_in[0];   // (1,64,16384) f32
    const int*   idx = (const int*)d_in[1];     // (2M,) int32
    const float* W   = (const float*)d_in[2];   // (64,64,2) f32
    float*       out = (float*)d_out;           // (1,64,16384) f32

    int twoM = in_sizes[1];
    int M = twoM / 2;
    int eb = (M + 1023) / 1024;                 // 4 edges/thread, 256 threads

    const int SMEM = 64 * 16 * 16 * 2 + 64 * 65 * 4 * 2;  // 66048 B
    cudaFuncSetAttribute(gather_out_kernel,
                         cudaFuncAttributeMaxDynamicSharedMemorySize, SMEM);

    prep_hist_kernel<<<1024 + eb, 256>>>(seq, idx, M);
    scan_kernel<<<1, 1024>>>();
    scatter_kernel<<<eb, 256>>>(idx, M);
    gather_out_kernel<<<N_NODES / 64, 512, SMEM>>>(W, out);
}